// round 3
// baseline (speedup 1.0000x reference)
#include <cuda_runtime.h>
#include <cuda_bf16.h>
#include <cstddef>

// ---------------- problem constants ----------------
#define NN 50000
#define NE 10000
#define DD 128
#define NNZI 400000
#define NNZE 80000
#define NNZV 400000

static const size_t ND = (size_t)NN * DD;   // 6,400,000
static const size_t ED = (size_t)NE * DD;   // 1,280,000

// scratch layout offsets (floats)
static const size_t OFF_PV  = 0;
static const size_t OFF_QE  = ND;
static const size_t OFF_A   = ND + ED;
static const size_t OFF_EF  = ND + 2*ED;
static const size_t OFF_VT  = ND + 3*ED;
static const size_t OFF_RV  = 2*ND + 3*ED;
static const size_t OFF_B   = 3*ND + 3*ED;
static const size_t OFF_V2  = 3*ND + 4*ED;
static const size_t OFF_V3  = 4*ND + 4*ED;
static const size_t OFF_E2  = 5*ND + 4*ED;
static const size_t OFF_DW  = 5*ND + 5*ED;
static const size_t OFF_CNT = 5*ND + 5*ED + NE;
#define SCRATCH_TOTAL (5*6400000ull + 5*1280000ull + 2*10000ull)

__device__ float g_scratch[SCRATCH_TOTAL];

// ---------------- degree / count pass ----------------
__global__ void deg_cnt_kernel(const int* __restrict__ src, const int* __restrict__ dst,
                               const float* __restrict__ invDV,
                               float* __restrict__ degw, float* __restrict__ cnt, int n) {
    int i = blockIdx.x * blockDim.x + threadIdx.x;
    if (i < n) {
        int d = dst[i];
        atomicAdd(&degw[d], invDV[src[i]]);
        atomicAdd(&cnt[d], 1.0f);
    }
}

// ---------------- y[r,:] = s[r] * x[r,:] ----------------
__global__ void scale_rows_kernel(const float* __restrict__ s, const float* __restrict__ x,
                                  float* __restrict__ y, int total) {
    int i = blockIdx.x * blockDim.x + threadIdx.x;
    if (i < total) y[i] = s[i >> 7] * x[i];
}

// ---------------- generic row scatter: dst[sc[i],:] += v_i * src[ga[i],:] ----------------
// one warp per item; 128 floats per row; red.global.add.v4.f32 (sm_90+)
__global__ __launch_bounds__(256) void scatter_kernel(
    const int* __restrict__ gather_idx, const int* __restrict__ scatter_idx,
    const float* __restrict__ vals,
    const float* __restrict__ src, float* __restrict__ dst, int n) {
    int t = blockIdx.x * blockDim.x + threadIdx.x;
    int w = t >> 5, lane = t & 31;
    if (w >= n) return;
    int gi = gather_idx[w];
    int si = scatter_idx[w];
    float4 x = *((const float4*)(src + (size_t)gi * DD) + lane);
    if (vals) {
        float v = vals[w];
        x.x *= v; x.y *= v; x.z *= v; x.w *= v;
    }
    float* d = dst + (size_t)si * DD + lane * 4;
    asm volatile("red.global.add.v4.f32 [%0], {%1,%2,%3,%4};"
                 :: "l"(d), "f"(x.x), "f"(x.y), "f"(x.z), "f"(x.w) : "memory");
}

// ---------------- GEMM: C[m,n] = post( sum_k A[m,k]*W[n*ldW+k] ) ----------------
// post: (+bias[n]) -> (*rowScale[m]) -> (relu)
// BM=64, full N=128, BK=16, 256 threads, each thread 8x4 outputs.
__global__ __launch_bounds__(256) void gemm_kernel(
    const float* __restrict__ A, const float* __restrict__ W, int ldW,
    const float* __restrict__ bias, const float* __restrict__ rowScale,
    float* __restrict__ C, int M, int doRelu) {
    __shared__ float As[16][64];
    __shared__ float Bs[16][128];
    int m0 = blockIdx.x * 64;
    int tid = threadIdx.x;
    int tm = tid >> 5;   // 0..7  -> rows tm*8..tm*8+7
    int tn = tid & 31;   // 0..31 -> cols tn*4..tn*4+3

    float acc[8][4];
#pragma unroll
    for (int i = 0; i < 8; i++)
#pragma unroll
        for (int j = 0; j < 4; j++) acc[i][j] = 0.f;

    int ra = tid >> 2;            // A-load row 0..63
    int ka = (tid & 3) * 4;       // A-load k offset

    for (int kk = 0; kk < 128; kk += 16) {
        // load A tile (transposed into As[k][m])
        float4 av = make_float4(0.f, 0.f, 0.f, 0.f);
        int gm = m0 + ra;
        if (gm < M) av = *(const float4*)(A + (size_t)gm * DD + kk + ka);
        As[ka + 0][ra] = av.x;
        As[ka + 1][ra] = av.y;
        As[ka + 2][ra] = av.z;
        As[ka + 3][ra] = av.w;
        // load W tile: Bs[k][n] = W[n*ldW + kk + k]
#pragma unroll
        for (int i = 0; i < 2; i++) {
            int idx = tid * 2 + i;        // 0..511
            int n = idx >> 2;             // 0..127
            int kq = (idx & 3) * 4;       // 0,4,8,12
            float4 wv = *(const float4*)(W + (size_t)n * ldW + kk + kq);
            Bs[kq + 0][n] = wv.x;
            Bs[kq + 1][n] = wv.y;
            Bs[kq + 2][n] = wv.z;
            Bs[kq + 3][n] = wv.w;
        }
        __syncthreads();
#pragma unroll
        for (int k = 0; k < 16; k++) {
            float4 a01 = *(const float4*)&As[k][tm * 8];
            float4 a23 = *(const float4*)&As[k][tm * 8 + 4];
            float4 bv  = *(const float4*)&Bs[k][tn * 4];
            float a[8] = {a01.x, a01.y, a01.z, a01.w, a23.x, a23.y, a23.z, a23.w};
            float b[4] = {bv.x, bv.y, bv.z, bv.w};
#pragma unroll
            for (int i = 0; i < 8; i++)
#pragma unroll
                for (int j = 0; j < 4; j++) acc[i][j] += a[i] * b[j];
        }
        __syncthreads();
    }

    float bvals[4];
#pragma unroll
    for (int j = 0; j < 4; j++) bvals[j] = bias ? bias[tn * 4 + j] : 0.f;

#pragma unroll
    for (int i = 0; i < 8; i++) {
        int m = m0 + tm * 8 + i;
        if (m >= M) continue;
        float rs = rowScale ? rowScale[m] : 1.f;
        float v0 = (acc[i][0] + bvals[0]) * rs;
        float v1 = (acc[i][1] + bvals[1]) * rs;
        float v2 = (acc[i][2] + bvals[2]) * rs;
        float v3 = (acc[i][3] + bvals[3]) * rs;
        if (doRelu) {
            v0 = fmaxf(v0, 0.f); v1 = fmaxf(v1, 0.f);
            v2 = fmaxf(v2, 0.f); v3 = fmaxf(v3, 0.f);
        }
        *(float4*)(C + (size_t)m * DD + tn * 4) = make_float4(v0, v1, v2, v3);
    }
}

// ---------------- host side ----------------
static inline int scat_grid(int n) { return (n + 7) / 8; }  // 8 warps/block of 256

extern "C" void kernel_launch(void* const* d_in, const int* in_sizes, int n_in,
                              void* d_out, int out_size) {
    const float* vfeat   = (const float*)d_in[0];
    const float* efeat   = (const float*)d_in[1];
    const float* invDV   = (const float*)d_in[2];
    const float* invDE   = (const float*)d_in[3];
    const int*   inc_src = (const int*)d_in[4];
    const int*   inc_dst = (const int*)d_in[5];
    const int*   emat_rows = (const int*)d_in[6];
    const int*   emat_cols = (const int*)d_in[7];
    const float* emat_vals = (const float*)d_in[8];
    const int*   vmat_rows = (const int*)d_in[9];
    const int*   vmat_cols = (const int*)d_in[10];
    const float* vmat_vals = (const float*)d_in[11];
    const float* Wv      = (const float*)d_in[12];
    const float* We      = (const float*)d_in[13];
    const float* psi1_W  = (const float*)d_in[14];
    const float* psi1_b  = (const float*)d_in[15];
    const float* psi2_W  = (const float*)d_in[16];
    const float* psi2_b  = (const float*)d_in[17];

    float* base = nullptr;
    cudaGetSymbolAddress((void**)&base, g_scratch);
    float* Pv  = base + OFF_PV;
    float* Qe  = base + OFF_QE;
    float* A   = base + OFF_A;
    float* ef  = base + OFF_EF;
    float* vt  = base + OFF_VT;
    float* Rv  = base + OFF_RV;
    float* Bb  = base + OFF_B;
    float* v2  = base + OFF_V2;
    float* v3  = base + OFF_V3;
    float* e2  = base + OFF_E2;
    float* dw  = base + OFF_DW;
    float* cnt = base + OFF_CNT;

    float* vout = (float*)d_out;               // [NN,128]
    float* eout = vout + ND;                   // [NE,128]

    // zero accumulation buffers (must be re-zeroed every call)
    cudaMemsetAsync(dw, 0, NE * sizeof(float));
    cudaMemsetAsync(cnt, 0, NE * sizeof(float));
    cudaMemsetAsync(vt, 0, ND * sizeof(float));
    cudaMemsetAsync(v2, 0, ND * sizeof(float));
    cudaMemsetAsync(v3, 0, ND * sizeof(float));

    // degrees: dw[e] = sum invDV[src], cnt[e] = #incidences
    deg_cnt_kernel<<<(NNZI + 255) / 256, 256>>>(inc_src, inc_dst, invDV, dw, cnt, NNZI);

    // Pv = invDV .* (vfeat @ W1v.T + b1)   (W1v = psi1_W[:, :128], ld 256)
    gemm_kernel<<<(NN + 63) / 64, 256>>>(vfeat, psi1_W, 256, psi1_b, invDV, Pv, NN, 0);
    // Qe = efeat @ W1e.T                   (W1e = psi1_W[:, 128:], ld 256)
    gemm_kernel<<<(NE + 63) / 64, 256>>>(efeat, psi1_W + 128, 256, nullptr, nullptr, Qe, NE, 0);

    // A = dw[e] * Qe[e]
    scale_rows_kernel<<<(int)((ED + 255) / 256), 256>>>(dw, Qe, A, (int)ED);
    // A[dst] += Pv[src]
    scatter_kernel<<<scat_grid(NNZI), 256>>>(inc_src, inc_dst, nullptr, Pv, A, NNZI);

    // _efeat = efeat + emat @ A
    cudaMemcpyAsync(ef, efeat, ED * sizeof(float), cudaMemcpyDeviceToDevice);
    scatter_kernel<<<scat_grid(NNZE), 256>>>(emat_cols, emat_rows, emat_vals, A, ef, NNZE);

    // _vfeat[src] += _efeat[dst]
    scatter_kernel<<<scat_grid(NNZI), 256>>>(inc_dst, inc_src, nullptr, ef, vt, NNZI);

    // vfeat_out = relu(_vfeat @ Wv.T)
    gemm_kernel<<<(NN + 63) / 64, 256>>>(vt, Wv, 128, nullptr, nullptr, vout, NN, 1);

    // Rv = vfeat_out @ W2v.T
    gemm_kernel<<<(NN + 63) / 64, 256>>>(vout, psi2_W, 256, nullptr, nullptr, Rv, NN, 0);
    // Bb = cnt[e] * (efeat @ W2e.T + b2)
    gemm_kernel<<<(NE + 63) / 64, 256>>>(efeat, psi2_W + 128, 256, psi2_b, cnt, Bb, NE, 0);
    // Bb[dst] += Rv[src]
    scatter_kernel<<<scat_grid(NNZI), 256>>>(inc_src, inc_dst, nullptr, Rv, Bb, NNZI);

    // _vfeat2[src] += efeat[dst]
    scatter_kernel<<<scat_grid(NNZI), 256>>>(inc_dst, inc_src, nullptr, efeat, v2, NNZI);
    // _vfeat3 = vmat @ _vfeat2
    scatter_kernel<<<scat_grid(NNZV), 256>>>(vmat_cols, vmat_rows, vmat_vals, v2, v3, NNZV);

    // _efeat2 = invDE .* Bb ; then += _vfeat3[src] per incidence
    scale_rows_kernel<<<(int)((ED + 255) / 256), 256>>>(invDE, Bb, e2, (int)ED);
    scatter_kernel<<<scat_grid(NNZI), 256>>>(inc_src, inc_dst, nullptr, v3, e2, NNZI);

    // efeat_out = relu(_efeat2 @ We.T)
    gemm_kernel<<<(NE + 63) / 64, 256>>>(e2, We, 128, nullptr, nullptr, eout, NE, 1);
}

// round 4
// speedup vs baseline: 1.2722x; 1.2722x over previous
#include <cuda_runtime.h>
#include <cuda_bf16.h>
#include <cstddef>

// ---------------- problem constants ----------------
#define NN 50000
#define NE 10000
#define DD 128
#define NNZI 400000
#define NNZE 80000
#define NNZV 400000

static const size_t ND = (size_t)NN * DD;   // 6,400,000
static const size_t ED = (size_t)NE * DD;   // 1,280,000

// scratch layout (floats): 7 E-side buffers, 2 N-side buffers, 2 scalar arrays
static const size_t OFF_A   = 0;                 // E
static const size_t OFF_U   = ED;                // E
static const size_t OFF_EF  = 2*ED;              // E
static const size_t OFF_EW  = 3*ED;              // E
static const size_t OFF_T   = 4*ED;              // E
static const size_t OFF_B1  = 5*ED;              // E
static const size_t OFF_E2  = 6*ED;              // E
static const size_t OFF_V2  = 7*ED;              // N
static const size_t OFF_V3  = 7*ED + ND;         // N
static const size_t OFF_DW  = 7*ED + 2*ND;       // NE
static const size_t OFF_CNT = 7*ED + 2*ND + NE;  // NE
#define SCRATCH_TOTAL (7*1280000ull + 2*6400000ull + 2*10000ull)

__device__ float g_scratch[SCRATCH_TOTAL];

// ---------------- degree / count pass ----------------
__global__ void deg_cnt_kernel(const int* __restrict__ src, const int* __restrict__ dst,
                               const float* __restrict__ invDV,
                               float* __restrict__ degw, float* __restrict__ cnt, int n) {
    int i = blockIdx.x * blockDim.x + threadIdx.x;
    if (i < n) {
        int d = dst[i];
        atomicAdd(&degw[d], invDV[src[i]]);
        atomicAdd(&cnt[d], 1.0f);
    }
}

// ---------------- in-place relu ----------------
__global__ void relu_kernel(float* __restrict__ x, int total) {
    int i = blockIdx.x * blockDim.x + threadIdx.x;
    if (i < total) x[i] = fmaxf(x[i], 0.f);
}

// ---------------- row scatter: dst[sc[i],:] += scale_i * src[ga[i],:] ----------------
// scale_i = vals[i] (per item) or gscale[ga[i]] (per gather row) or 1.
// one warp per 4 items for MLP=4; 128 floats per row; red.global.add.v4.f32
__global__ __launch_bounds__(256) void scatter_kernel(
    const int* __restrict__ gidx, const int* __restrict__ sidx,
    const float* __restrict__ vals, const float* __restrict__ gscale,
    const float* __restrict__ src, float* __restrict__ dst, int n) {
    int t = blockIdx.x * blockDim.x + threadIdx.x;
    int w = t >> 5, lane = t & 31;
    int i0 = w * 4;
    float4 x[4]; int si[4]; bool act[4];
#pragma unroll
    for (int j = 0; j < 4; j++) {
        int i = i0 + j;
        act[j] = (i < n);
        if (act[j]) {
            int gi = gidx[i];
            si[j] = sidx[i];
            x[j] = *((const float4*)(src + (size_t)gi * DD) + lane);
            float v = 1.f;
            if (vals)   v = vals[i];
            if (gscale) v = gscale[gi];
            x[j].x *= v; x[j].y *= v; x[j].z *= v; x[j].w *= v;
        }
    }
#pragma unroll
    for (int j = 0; j < 4; j++) {
        if (act[j]) {
            float* d = dst + (size_t)si[j] * DD + lane * 4;
            asm volatile("red.global.add.v4.f32 [%0], {%1,%2,%3,%4};"
                         :: "l"(d), "f"(x[j].x), "f"(x[j].y), "f"(x[j].z), "f"(x[j].w)
                         : "memory");
        }
    }
}

// ---------------- fused dual scatter (same index pair, two src/dst streams) ----------
// dst0[s[i],:] += src0[g[i],:]  and  dst1[s[i],:] += src1[g[i],:]
__global__ __launch_bounds__(256) void scatter2_kernel(
    const int* __restrict__ gidx, const int* __restrict__ sidx,
    const float* __restrict__ src0, float* __restrict__ dst0,
    const float* __restrict__ src1, float* __restrict__ dst1, int n) {
    int t = blockIdx.x * blockDim.x + threadIdx.x;
    int w = t >> 5, lane = t & 31;
    int i0 = w * 2;
    float4 a[2], b[2]; int si[2]; bool act[2];
#pragma unroll
    for (int j = 0; j < 2; j++) {
        int i = i0 + j;
        act[j] = (i < n);
        if (act[j]) {
            int gi = gidx[i];
            si[j] = sidx[i];
            a[j] = *((const float4*)(src0 + (size_t)gi * DD) + lane);
            b[j] = *((const float4*)(src1 + (size_t)gi * DD) + lane);
        }
    }
#pragma unroll
    for (int j = 0; j < 2; j++) {
        if (act[j]) {
            float* d0 = dst0 + (size_t)si[j] * DD + lane * 4;
            float* d1 = dst1 + (size_t)si[j] * DD + lane * 4;
            asm volatile("red.global.add.v4.f32 [%0], {%1,%2,%3,%4};"
                         :: "l"(d0), "f"(a[j].x), "f"(a[j].y), "f"(a[j].z), "f"(a[j].w)
                         : "memory");
            asm volatile("red.global.add.v4.f32 [%0], {%1,%2,%3,%4};"
                         :: "l"(d1), "f"(b[j].x), "f"(b[j].y), "f"(b[j].z), "f"(b[j].w)
                         : "memory");
        }
    }
}

// ---------------- GEMM: C[m,n] = post( sum_k A[m,k]*W[n*ldW+k] ) ----------------
// post: v = (acc + bias[n] + Cprev[m,n]) * rowScale[m]; optional relu.
// BM=64, full N=128, BK=16, 256 threads, each thread 8x4 outputs.
__global__ __launch_bounds__(256) void gemm_kernel(
    const float* __restrict__ A, const float* __restrict__ W, int ldW,
    const float* __restrict__ bias, const float* __restrict__ rowScale,
    const float* __restrict__ Cprev,
    float* __restrict__ C, int M, int doRelu) {
    __shared__ float As[16][64];
    __shared__ float Bs[16][128];
    int m0 = blockIdx.x * 64;
    int tid = threadIdx.x;
    int tm = tid >> 5;   // 0..7  -> rows tm*8..tm*8+7
    int tn = tid & 31;   // 0..31 -> cols tn*4..tn*4+3

    float acc[8][4];
#pragma unroll
    for (int i = 0; i < 8; i++)
#pragma unroll
        for (int j = 0; j < 4; j++) acc[i][j] = 0.f;

    int ra = tid >> 2;            // A-load row 0..63
    int ka = (tid & 3) * 4;       // A-load k offset

    for (int kk = 0; kk < 128; kk += 16) {
        float4 av = make_float4(0.f, 0.f, 0.f, 0.f);
        int gm = m0 + ra;
        if (gm < M) av = *(const float4*)(A + (size_t)gm * DD + kk + ka);
        As[ka + 0][ra] = av.x;
        As[ka + 1][ra] = av.y;
        As[ka + 2][ra] = av.z;
        As[ka + 3][ra] = av.w;
#pragma unroll
        for (int i = 0; i < 2; i++) {
            int idx = tid * 2 + i;        // 0..511
            int n = idx >> 2;             // 0..127
            int kq = (idx & 3) * 4;       // 0,4,8,12
            float4 wv = *(const float4*)(W + (size_t)n * ldW + kk + kq);
            Bs[kq + 0][n] = wv.x;
            Bs[kq + 1][n] = wv.y;
            Bs[kq + 2][n] = wv.z;
            Bs[kq + 3][n] = wv.w;
        }
        __syncthreads();
#pragma unroll
        for (int k = 0; k < 16; k++) {
            float4 a01 = *(const float4*)&As[k][tm * 8];
            float4 a23 = *(const float4*)&As[k][tm * 8 + 4];
            float4 bv  = *(const float4*)&Bs[k][tn * 4];
            float a[8] = {a01.x, a01.y, a01.z, a01.w, a23.x, a23.y, a23.z, a23.w};
            float b[4] = {bv.x, bv.y, bv.z, bv.w};
#pragma unroll
            for (int i = 0; i < 8; i++)
#pragma unroll
                for (int j = 0; j < 4; j++) acc[i][j] += a[i] * b[j];
        }
        __syncthreads();
    }

    float bvals[4];
#pragma unroll
    for (int j = 0; j < 4; j++) bvals[j] = bias ? bias[tn * 4 + j] : 0.f;

#pragma unroll
    for (int i = 0; i < 8; i++) {
        int m = m0 + tm * 8 + i;
        if (m >= M) continue;
        float rs = rowScale ? rowScale[m] : 1.f;
        float4 cp = make_float4(0.f, 0.f, 0.f, 0.f);
        if (Cprev) cp = *(const float4*)(Cprev + (size_t)m * DD + tn * 4);
        float v0 = (acc[i][0] + bvals[0] + cp.x) * rs;
        float v1 = (acc[i][1] + bvals[1] + cp.y) * rs;
        float v2 = (acc[i][2] + bvals[2] + cp.z) * rs;
        float v3 = (acc[i][3] + bvals[3] + cp.w) * rs;
        if (doRelu) {
            v0 = fmaxf(v0, 0.f); v1 = fmaxf(v1, 0.f);
            v2 = fmaxf(v2, 0.f); v3 = fmaxf(v3, 0.f);
        }
        *(float4*)(C + (size_t)m * DD + tn * 4) = make_float4(v0, v1, v2, v3);
    }
}

// ---------------- host side ----------------
static inline int grid_items(int n, int per_warp) {
    int warps = (n + per_warp - 1) / per_warp;
    return (warps + 7) / 8;   // 8 warps / 256-thread block
}

extern "C" void kernel_launch(void* const* d_in, const int* in_sizes, int n_in,
                              void* d_out, int out_size) {
    const float* vfeat   = (const float*)d_in[0];
    const float* efeat   = (const float*)d_in[1];
    const float* invDV   = (const float*)d_in[2];
    const float* invDE   = (const float*)d_in[3];
    const int*   inc_src = (const int*)d_in[4];
    const int*   inc_dst = (const int*)d_in[5];
    const int*   emat_rows = (const int*)d_in[6];
    const int*   emat_cols = (const int*)d_in[7];
    const float* emat_vals = (const float*)d_in[8];
    const int*   vmat_rows = (const int*)d_in[9];
    const int*   vmat_cols = (const int*)d_in[10];
    const float* vmat_vals = (const float*)d_in[11];
    const float* Wv      = (const float*)d_in[12];
    const float* We      = (const float*)d_in[13];
    const float* psi1_W  = (const float*)d_in[14];
    const float* psi1_b  = (const float*)d_in[15];
    const float* psi2_W  = (const float*)d_in[16];
    const float* psi2_b  = (const float*)d_in[17];

    float* base = nullptr;
    cudaGetSymbolAddress((void**)&base, g_scratch);
    float* A   = base + OFF_A;
    float* U   = base + OFF_U;
    float* ef  = base + OFF_EF;
    float* ew  = base + OFF_EW;
    float* T   = base + OFF_T;
    float* B1  = base + OFF_B1;
    float* e2  = base + OFF_E2;
    float* v2  = base + OFF_V2;
    float* v3  = base + OFF_V3;
    float* dw  = base + OFF_DW;
    float* cnt = base + OFF_CNT;

    float* vout = (float*)d_out;               // [NN,128]
    float* eout = vout + ND;                   // [NE,128]

    // zero accumulation buffers
    cudaMemsetAsync(dw,  0, NE * sizeof(float));
    cudaMemsetAsync(cnt, 0, NE * sizeof(float));
    cudaMemsetAsync(U,   0, ED * sizeof(float));
    cudaMemsetAsync(T,   0, ED * sizeof(float));
    cudaMemsetAsync(v2,  0, ND * sizeof(float));
    cudaMemsetAsync(v3,  0, ND * sizeof(float));
    cudaMemsetAsync(vout, 0, ND * sizeof(float));

    // dw[e] = sum invDV[src], cnt[e] = #incidences
    deg_cnt_kernel<<<(NNZI + 255) / 256, 256>>>(inc_src, inc_dst, invDV, dw, cnt, NNZI);

    // A = dw .* (efeat @ W1e.T + b1)
    gemm_kernel<<<(NE + 63) / 64, 256>>>(efeat, psi1_W + 128, 256, psi1_b, dw, nullptr, A, NE, 0);

    // U[dst] += invDV[src] * vfeat[src]
    scatter_kernel<<<grid_items(NNZI, 4), 256>>>(inc_src, inc_dst, nullptr, invDV, vfeat, U, NNZI);

    // A += U @ W1v.T   (in-place accumulate)
    gemm_kernel<<<(NE + 63) / 64, 256>>>(U, psi1_W, 256, nullptr, nullptr, A, A, NE, 0);

    // ef = efeat + emat @ A
    cudaMemcpyAsync(ef, efeat, ED * sizeof(float), cudaMemcpyDeviceToDevice);
    scatter_kernel<<<grid_items(NNZE, 4), 256>>>(emat_cols, emat_rows, emat_vals, nullptr, A, ef, NNZE);

    // ew = ef @ Wv.T   (project on E side: (S·ef)@Wv = S·(ef@Wv))
    gemm_kernel<<<(NE + 63) / 64, 256>>>(ef, Wv, 128, nullptr, nullptr, nullptr, ew, NE, 0);

    // vout[src] += ew[dst]   AND   v2[src] += efeat[dst]   (same index pair)
    scatter2_kernel<<<grid_items(NNZI, 2), 256>>>(inc_dst, inc_src, ew, vout, efeat, v2, NNZI);

    // vout = relu(vout)  -> final vfeat_out
    relu_kernel<<<(int)((ND + 255) / 256), 256>>>(vout, (int)ND);

    // T[dst] += vout[src]   (for B's psi2 vout-term: (S^T vout)@W2v)
    scatter_kernel<<<grid_items(NNZI, 4), 256>>>(inc_src, inc_dst, nullptr, nullptr, vout, T, NNZI);

    // B1 = cnt .* (efeat @ W2e.T + b2)
    gemm_kernel<<<(NE + 63) / 64, 256>>>(efeat, psi2_W + 128, 256, psi2_b, cnt, nullptr, B1, NE, 0);

    // e2 = invDE .* (T @ W2v.T + B1)
    gemm_kernel<<<(NE + 63) / 64, 256>>>(T, psi2_W, 256, nullptr, invDE, B1, e2, NE, 0);

    // v3 = vmat @ v2
    scatter_kernel<<<grid_items(NNZV, 4), 256>>>(vmat_cols, vmat_rows, vmat_vals, nullptr, v2, v3, NNZV);

    // e2[dst] += v3[src]
    scatter_kernel<<<grid_items(NNZI, 4), 256>>>(inc_src, inc_dst, nullptr, nullptr, v3, e2, NNZI);

    // eout = relu(e2 @ We.T)
    gemm_kernel<<<(NE + 63) / 64, 256>>>(e2, We, 128, nullptr, nullptr, nullptr, eout, NE, 1);
}

// round 5
// speedup vs baseline: 1.3551x; 1.0652x over previous
#include <cuda_runtime.h>
#include <cuda_bf16.h>
#include <cstddef>

// ---------------- problem constants ----------------
#define NN 50000
#define NE 10000
#define DD 128
#define NNZI 400000
#define NNZE 80000
#define NNZV 400000

static const size_t ND = (size_t)NN * DD;   // 6,400,000
static const size_t ED = (size_t)NE * DD;   // 1,280,000

// scratch layout (floats). Zeroed region first (one big memset), then rest.
static const size_t OFF_U     = 0;                    // E (zeroed)
static const size_t OFF_T     = ED;                   // E (zeroed)
static const size_t OFF_EMA   = 2*ED;                 // E (zeroed)
static const size_t OFF_E2ACC = 3*ED;                 // E (zeroed)
static const size_t OFF_V2    = 4*ED;                 // N (zeroed)
static const size_t OFF_V3    = 4*ED + ND;            // N (zeroed)
static const size_t OFF_DW    = 4*ED + 2*ND;          // NE (zeroed)
static const size_t OFF_CNT   = 4*ED + 2*ND + NE;     // NE (zeroed)
static const size_t ZERO_TOTAL= 4*ED + 2*ND + 2*NE;
static const size_t OFF_A     = ZERO_TOTAL;           // E
static const size_t OFF_EW    = ZERO_TOTAL + ED;      // E
static const size_t OFF_B1    = ZERO_TOTAL + 2*ED;    // E
static const size_t OFF_E2    = ZERO_TOTAL + 3*ED;    // E
#define SCRATCH_TOTAL (4*1280000ull + 2*6400000ull + 2*10000ull + 4*1280000ull)

__device__ float g_scratch[SCRATCH_TOTAL];

typedef unsigned long long u64;

__device__ __forceinline__ void fma2(u64& d, u64 a, u64 b) {
    asm("fma.rn.f32x2 %0, %1, %2, %0;" : "+l"(d) : "l"(a), "l"(b));
}
__device__ __forceinline__ u64 dup2(float v) {
    u64 r;
    asm("mov.b64 %0, {%1,%1};" : "=l"(r) : "r"(__float_as_uint(v)));
    return r;
}
__device__ __forceinline__ float lo32(u64 v) { return __uint_as_float((unsigned)v); }
__device__ __forceinline__ float hi32(u64 v) { return __uint_as_float((unsigned)(v >> 32)); }

// ---------------- in-place relu (float4) ----------------
__global__ void relu_kernel(float4* __restrict__ x, int total4) {
    int i = blockIdx.x * blockDim.x + threadIdx.x;
    if (i < total4) {
        float4 v = x[i];
        v.x = fmaxf(v.x, 0.f); v.y = fmaxf(v.y, 0.f);
        v.z = fmaxf(v.z, 0.f); v.w = fmaxf(v.w, 0.f);
        x[i] = v;
    }
}

// ---------------- U scatter + degree pass (fused) ----------------
// U[dst[i],:] += invDV[src[i]] * vfeat[src[i],:];  dw[dst]+=invDV[src]; cnt[dst]+=1
__global__ __launch_bounds__(256) void scatterU_kernel(
    const int* __restrict__ gidx, const int* __restrict__ sidx,
    const float* __restrict__ invDV, const float* __restrict__ vfeat,
    float* __restrict__ U, float* __restrict__ dw, float* __restrict__ cnt, int n) {
    int t = blockIdx.x * blockDim.x + threadIdx.x;
    int w = t >> 5, lane = t & 31;
    int i0 = w * 4;
    float4 x[4]; int si[4]; float vv[4]; bool act[4];
#pragma unroll
    for (int j = 0; j < 4; j++) {
        int i = i0 + j;
        act[j] = (i < n);
        if (act[j]) {
            int gi = gidx[i];
            si[j] = sidx[i];
            float v = invDV[gi];
            vv[j] = v;
            x[j] = *((const float4*)(vfeat + (size_t)gi * DD) + lane);
            x[j].x *= v; x[j].y *= v; x[j].z *= v; x[j].w *= v;
        }
    }
#pragma unroll
    for (int j = 0; j < 4; j++) {
        if (act[j]) {
            float* d = U + (size_t)si[j] * DD + lane * 4;
            asm volatile("red.global.add.v4.f32 [%0], {%1,%2,%3,%4};"
                         :: "l"(d), "f"(x[j].x), "f"(x[j].y), "f"(x[j].z), "f"(x[j].w)
                         : "memory");
            if (lane == 0) {
                atomicAdd(&dw[si[j]], vv[j]);
                atomicAdd(&cnt[si[j]], 1.0f);
            }
        }
    }
}

// ---------------- generic row scatter: dst[sc[i],:] += v_i * src[ga[i],:] --------
__global__ __launch_bounds__(256) void scatter_kernel(
    const int* __restrict__ gidx, const int* __restrict__ sidx,
    const float* __restrict__ vals,
    const float* __restrict__ src, float* __restrict__ dst, int n) {
    int t = blockIdx.x * blockDim.x + threadIdx.x;
    int w = t >> 5, lane = t & 31;
    int i0 = w * 4;
    float4 x[4]; int si[4]; bool act[4];
#pragma unroll
    for (int j = 0; j < 4; j++) {
        int i = i0 + j;
        act[j] = (i < n);
        if (act[j]) {
            int gi = gidx[i];
            si[j] = sidx[i];
            x[j] = *((const float4*)(src + (size_t)gi * DD) + lane);
            if (vals) {
                float v = vals[i];
                x[j].x *= v; x[j].y *= v; x[j].z *= v; x[j].w *= v;
            }
        }
    }
#pragma unroll
    for (int j = 0; j < 4; j++) {
        if (act[j]) {
            float* d = dst + (size_t)si[j] * DD + lane * 4;
            asm volatile("red.global.add.v4.f32 [%0], {%1,%2,%3,%4};"
                         :: "l"(d), "f"(x[j].x), "f"(x[j].y), "f"(x[j].z), "f"(x[j].w)
                         : "memory");
        }
    }
}

// ---------------- GEMM: C = post( (A+A2) @ W.T ) with f32x2 math ----------------
// post: v = (acc + bias[n] + Cprev[m,n]) * rowScale[m] + Cadd[m,n]; optional relu.
// BM=64, BN=128, BK=16, 256 threads; thread computes 8m x 4n as 4 f32x2-pairs x 4.
__global__ __launch_bounds__(256) void gemm_kernel(
    const float* __restrict__ A, const float* __restrict__ A2,
    const float* __restrict__ W, int ldW,
    const float* __restrict__ bias, const float* __restrict__ rowScale,
    const float* __restrict__ Cprev, const float* __restrict__ Cadd,
    float* __restrict__ C, int M, int doRelu) {
    __shared__ float As[16][64];
    __shared__ float Bs[16][128];
    int m0 = blockIdx.x * 64;
    int tid = threadIdx.x;
    int tm = tid >> 5;   // warp id 0..7 -> rows tm*8..tm*8+7
    int tn = tid & 31;   // lane -> cols tn*4..tn*4+3

    u64 acc[4][4];
#pragma unroll
    for (int p = 0; p < 4; p++)
#pragma unroll
        for (int j = 0; j < 4; j++) acc[p][j] = 0ull;

    int ra = tid >> 2;            // A-load row 0..63
    int ka = (tid & 3) * 4;       // A-load k offset

    for (int kk = 0; kk < 128; kk += 16) {
        float4 av = make_float4(0.f, 0.f, 0.f, 0.f);
        int gm = m0 + ra;
        if (gm < M) {
            av = *(const float4*)(A + (size_t)gm * DD + kk + ka);
            if (A2) {
                float4 a2 = *(const float4*)(A2 + (size_t)gm * DD + kk + ka);
                av.x += a2.x; av.y += a2.y; av.z += a2.z; av.w += a2.w;
            }
        }
        As[ka + 0][ra] = av.x;
        As[ka + 1][ra] = av.y;
        As[ka + 2][ra] = av.z;
        As[ka + 3][ra] = av.w;
#pragma unroll
        for (int i = 0; i < 2; i++) {
            int idx = tid * 2 + i;        // 0..511
            int n = idx >> 2;             // 0..127
            int kq = (idx & 3) * 4;       // 0,4,8,12
            float4 wv = *(const float4*)(W + (size_t)n * ldW + kk + kq);
            Bs[kq + 0][n] = wv.x;
            Bs[kq + 1][n] = wv.y;
            Bs[kq + 2][n] = wv.z;
            Bs[kq + 3][n] = wv.w;
        }
        __syncthreads();
#pragma unroll
        for (int k = 0; k < 16; k++) {
            const u64* ap = (const u64*)&As[k][tm * 8];   // 4 f32x2 pairs (broadcast)
            u64 a0 = ap[0], a1 = ap[1], a2 = ap[2], a3 = ap[3];
            float4 bv = *(const float4*)&Bs[k][tn * 4];
            u64 b0 = dup2(bv.x), b1 = dup2(bv.y), b2 = dup2(bv.z), b3 = dup2(bv.w);
            fma2(acc[0][0], a0, b0); fma2(acc[0][1], a0, b1);
            fma2(acc[0][2], a0, b2); fma2(acc[0][3], a0, b3);
            fma2(acc[1][0], a1, b0); fma2(acc[1][1], a1, b1);
            fma2(acc[1][2], a1, b2); fma2(acc[1][3], a1, b3);
            fma2(acc[2][0], a2, b0); fma2(acc[2][1], a2, b1);
            fma2(acc[2][2], a2, b2); fma2(acc[2][3], a2, b3);
            fma2(acc[3][0], a3, b0); fma2(acc[3][1], a3, b1);
            fma2(acc[3][2], a3, b2); fma2(acc[3][3], a3, b3);
        }
        __syncthreads();
    }

    float bvals[4];
#pragma unroll
    for (int j = 0; j < 4; j++) bvals[j] = bias ? bias[tn * 4 + j] : 0.f;

#pragma unroll
    for (int p = 0; p < 4; p++) {
        int mA = m0 + tm * 8 + p * 2;
#pragma unroll
        for (int q = 0; q < 2; q++) {
            int m = mA + q;
            if (m >= M) continue;
            float rs = rowScale ? rowScale[m] : 1.f;
            float4 cp = make_float4(0.f, 0.f, 0.f, 0.f);
            if (Cprev) cp = *(const float4*)(Cprev + (size_t)m * DD + tn * 4);
            float4 ca = make_float4(0.f, 0.f, 0.f, 0.f);
            if (Cadd) ca = *(const float4*)(Cadd + (size_t)m * DD + tn * 4);
            float r0 = q ? hi32(acc[p][0]) : lo32(acc[p][0]);
            float r1 = q ? hi32(acc[p][1]) : lo32(acc[p][1]);
            float r2 = q ? hi32(acc[p][2]) : lo32(acc[p][2]);
            float r3 = q ? hi32(acc[p][3]) : lo32(acc[p][3]);
            float v0 = (r0 + bvals[0] + cp.x) * rs + ca.x;
            float v1 = (r1 + bvals[1] + cp.y) * rs + ca.y;
            float v2 = (r2 + bvals[2] + cp.z) * rs + ca.z;
            float v3 = (r3 + bvals[3] + cp.w) * rs + ca.w;
            if (doRelu) {
                v0 = fmaxf(v0, 0.f); v1 = fmaxf(v1, 0.f);
                v2 = fmaxf(v2, 0.f); v3 = fmaxf(v3, 0.f);
            }
            *(float4*)(C + (size_t)m * DD + tn * 4) = make_float4(v0, v1, v2, v3);
        }
    }
}

// ---------------- host side ----------------
static inline int grid_items(int n) {
    int warps = (n + 3) / 4;
    return (warps + 7) / 8;   // 8 warps / 256-thread block
}

extern "C" void kernel_launch(void* const* d_in, const int* in_sizes, int n_in,
                              void* d_out, int out_size) {
    const float* vfeat   = (const float*)d_in[0];
    const float* efeat   = (const float*)d_in[1];
    const float* invDV   = (const float*)d_in[2];
    const float* invDE   = (const float*)d_in[3];
    const int*   inc_src = (const int*)d_in[4];
    const int*   inc_dst = (const int*)d_in[5];
    const int*   emat_rows = (const int*)d_in[6];
    const int*   emat_cols = (const int*)d_in[7];
    const float* emat_vals = (const float*)d_in[8];
    const int*   vmat_rows = (const int*)d_in[9];
    const int*   vmat_cols = (const int*)d_in[10];
    const float* vmat_vals = (const float*)d_in[11];
    const float* Wv      = (const float*)d_in[12];
    const float* We      = (const float*)d_in[13];
    const float* psi1_W  = (const float*)d_in[14];
    const float* psi1_b  = (const float*)d_in[15];
    const float* psi2_W  = (const float*)d_in[16];
    const float* psi2_b  = (const float*)d_in[17];

    float* base = nullptr;
    cudaGetSymbolAddress((void**)&base, g_scratch);
    float* U     = base + OFF_U;
    float* T     = base + OFF_T;
    float* emA   = base + OFF_EMA;
    float* e2acc = base + OFF_E2ACC;
    float* v2    = base + OFF_V2;
    float* v3    = base + OFF_V3;
    float* dw    = base + OFF_DW;
    float* cnt   = base + OFF_CNT;
    float* A     = base + OFF_A;
    float* ew    = base + OFF_EW;
    float* B1    = base + OFF_B1;
    float* e2    = base + OFF_E2;

    float* vout = (float*)d_out;               // [NN,128]
    float* eout = vout + ND;                   // [NE,128]

    // zero all accumulation buffers in one memset + vout
    cudaMemsetAsync(base, 0, ZERO_TOTAL * sizeof(float));
    cudaMemsetAsync(vout, 0, ND * sizeof(float));

    // U[dst] += invDV[src]*vfeat[src]; dw[dst]+=invDV[src]; cnt[dst]+=1
    scatterU_kernel<<<grid_items(NNZI), 256>>>(inc_src, inc_dst, invDV, vfeat, U, dw, cnt, NNZI);

    // v2[src] += efeat[dst]  (independent of everything else)
    scatter_kernel<<<grid_items(NNZI), 256>>>(inc_dst, inc_src, nullptr, efeat, v2, NNZI);

    // v3 = vmat @ v2
    scatter_kernel<<<grid_items(NNZV), 256>>>(vmat_cols, vmat_rows, vmat_vals, v2, v3, NNZV);

    // e2acc[dst] += v3[src]
    scatter_kernel<<<grid_items(NNZI), 256>>>(inc_src, inc_dst, nullptr, v3, e2acc, NNZI);

    // A = dw .* (efeat @ W1e.T + b1)
    gemm_kernel<<<(NE + 63) / 64, 256>>>(efeat, nullptr, psi1_W + 128, 256, psi1_b, dw, nullptr, nullptr, A, NE, 0);
    // A += U @ W1v.T
    gemm_kernel<<<(NE + 63) / 64, 256>>>(U, nullptr, psi1_W, 256, nullptr, nullptr, A, nullptr, A, NE, 0);

    // emA = emat @ A
    scatter_kernel<<<grid_items(NNZE), 256>>>(emat_cols, emat_rows, emat_vals, A, emA, NNZE);

    // ew = (emA + efeat) @ Wv.T
    gemm_kernel<<<(NE + 63) / 64, 256>>>(emA, efeat, Wv, 128, nullptr, nullptr, nullptr, nullptr, ew, NE, 0);

    // vout[src] += ew[dst]
    scatter_kernel<<<grid_items(NNZI), 256>>>(inc_dst, inc_src, nullptr, ew, vout, NNZI);

    // vout = relu(vout)  -> final vfeat_out
    relu_kernel<<<(int)((ND / 4 + 255) / 256), 256>>>((float4*)vout, (int)(ND / 4));

    // T[dst] += vout[src]
    scatter_kernel<<<grid_items(NNZI), 256>>>(inc_src, inc_dst, nullptr, vout, T, NNZI);

    // B1 = cnt .* (efeat @ W2e.T + b2)
    gemm_kernel<<<(NE + 63) / 64, 256>>>(efeat, nullptr, psi2_W + 128, 256, psi2_b, cnt, nullptr, nullptr, B1, NE, 0);

    // e2 = invDE .* (T @ W2v.T + B1) + e2acc
    gemm_kernel<<<(NE + 63) / 64, 256>>>(T, nullptr, psi2_W, 256, nullptr, invDE, B1, e2acc, e2, NE, 0);

    // eout = relu(e2 @ We.T)
    gemm_kernel<<<(NE + 63) / 64, 256>>>(e2, nullptr, We, 128, nullptr, nullptr, nullptr, nullptr, eout, NE, 1);
}

// round 6
// speedup vs baseline: 1.5029x; 1.1090x over previous
#include <cuda_runtime.h>
#include <cuda_bf16.h>
#include <cstddef>

// ---------------- problem constants ----------------
#define NN 50000
#define NE 10000
#define DD 128
#define NNZI 400000
#define NNZE 80000
#define NNZV 400000

static const size_t ND = (size_t)NN * DD;   // 6,400,000
static const size_t ED = (size_t)NE * DD;   // 1,280,000

// scratch layout (floats).
// Zero-region A (stream 0): [U][T][EMA][DW][CNT]
// Zero-region B (stream 1): [V2][V3][E2ACC]
// Non-zeroed:              [A][EW][B1][E2]
static const size_t OFF_U     = 0;                     // E
static const size_t OFF_T     = ED;                    // E
static const size_t OFF_EMA   = 2*ED;                  // E
static const size_t OFF_DW    = 3*ED;                  // NE
static const size_t OFF_CNT   = 3*ED + NE;             // NE
static const size_t ZEROA_LEN = 3*ED + 2*NE;
static const size_t OFF_V2    = ZEROA_LEN;             // N
static const size_t OFF_V3    = ZEROA_LEN + ND;        // N
static const size_t OFF_E2ACC = ZEROA_LEN + 2*ND;      // E
static const size_t ZEROB_LEN = 2*ND + ED;
static const size_t OFF_A     = OFF_E2ACC + ED;        // E
static const size_t OFF_EW    = OFF_A  + ED;           // E
static const size_t OFF_B1    = OFF_EW + ED;           // E
static const size_t OFF_E2    = OFF_B1 + ED;           // E
#define SCRATCH_TOTAL (8*1280000ull + 2*6400000ull + 2*10000ull)

__device__ float g_scratch[SCRATCH_TOTAL];

typedef unsigned long long u64;

__device__ __forceinline__ void fma2(u64& d, u64 a, u64 b) {
    asm("fma.rn.f32x2 %0, %1, %2, %0;" : "+l"(d) : "l"(a), "l"(b));
}
__device__ __forceinline__ u64 dup2(float v) {
    u64 r;
    asm("mov.b64 %0, {%1,%1};" : "=l"(r) : "r"(__float_as_uint(v)));
    return r;
}
__device__ __forceinline__ float lo32(u64 v) { return __uint_as_float((unsigned)v); }
__device__ __forceinline__ float hi32(u64 v) { return __uint_as_float((unsigned)(v >> 32)); }

// ---------------- degree / count pass (scalar reds) ----------------
__global__ void deg_cnt_kernel(const int* __restrict__ src, const int* __restrict__ dst,
                               const float* __restrict__ invDV,
                               float* __restrict__ dw, float* __restrict__ cnt, int n) {
    int i = blockIdx.x * blockDim.x + threadIdx.x;
    if (i < n) {
        int d = dst[i];
        float v = invDV[src[i]];
        asm volatile("red.global.add.f32 [%0], %1;" :: "l"(&dw[d]), "f"(v) : "memory");
        asm volatile("red.global.add.f32 [%0], %1;" :: "l"(&cnt[d]), "f"(1.0f) : "memory");
    }
}

// ---------------- in-place relu (float4) ----------------
__global__ void relu_kernel(float4* __restrict__ x, int total4) {
    int i = blockIdx.x * blockDim.x + threadIdx.x;
    if (i < total4) {
        float4 v = x[i];
        v.x = fmaxf(v.x, 0.f); v.y = fmaxf(v.y, 0.f);
        v.z = fmaxf(v.z, 0.f); v.w = fmaxf(v.w, 0.f);
        x[i] = v;
    }
}

// ---------------- generic row scatter: dst[sc[i],:] += scale_i * src[ga[i],:] ------
// scale_i = vals[i] (per item) or gscale[ga[i]] (per gather row) or 1.
__global__ __launch_bounds__(256) void scatter_kernel(
    const int* __restrict__ gidx, const int* __restrict__ sidx,
    const float* __restrict__ vals, const float* __restrict__ gscale,
    const float* __restrict__ src, float* __restrict__ dst, int n) {
    int t = blockIdx.x * blockDim.x + threadIdx.x;
    int w = t >> 5, lane = t & 31;
    int i0 = w * 4;
    float4 x[4]; int si[4]; bool act[4];
#pragma unroll
    for (int j = 0; j < 4; j++) {
        int i = i0 + j;
        act[j] = (i < n);
        if (act[j]) {
            int gi = gidx[i];
            si[j] = sidx[i];
            x[j] = *((const float4*)(src + (size_t)gi * DD) + lane);
            float v = 1.f;
            if (vals)   v = vals[i];
            if (gscale) v = gscale[gi];
            x[j].x *= v; x[j].y *= v; x[j].z *= v; x[j].w *= v;
        }
    }
#pragma unroll
    for (int j = 0; j < 4; j++) {
        if (act[j]) {
            float* d = dst + (size_t)si[j] * DD + lane * 4;
            asm volatile("red.global.add.v4.f32 [%0], {%1,%2,%3,%4};"
                         :: "l"(d), "f"(x[j].x), "f"(x[j].y), "f"(x[j].z), "f"(x[j].w)
                         : "memory");
        }
    }
}

// ---------------- GEMM: C = post( (A+A2) @ W.T ) with f32x2 math ----------------
// post: v = (acc + bias[n] + Cprev[m,n]) * rowScale[m] + Cadd[m,n]; optional relu.
__global__ __launch_bounds__(256) void gemm_kernel(
    const float* __restrict__ A, const float* __restrict__ A2,
    const float* __restrict__ W, int ldW,
    const float* __restrict__ bias, const float* __restrict__ rowScale,
    const float* __restrict__ Cprev, const float* __restrict__ Cadd,
    float* __restrict__ C, int M, int doRelu) {
    __shared__ float As[16][64];
    __shared__ float Bs[16][128];
    int m0 = blockIdx.x * 64;
    int tid = threadIdx.x;
    int tm = tid >> 5;
    int tn = tid & 31;

    u64 acc[4][4];
#pragma unroll
    for (int p = 0; p < 4; p++)
#pragma unroll
        for (int j = 0; j < 4; j++) acc[p][j] = 0ull;

    int ra = tid >> 2;
    int ka = (tid & 3) * 4;

    for (int kk = 0; kk < 128; kk += 16) {
        float4 av = make_float4(0.f, 0.f, 0.f, 0.f);
        int gm = m0 + ra;
        if (gm < M) {
            av = *(const float4*)(A + (size_t)gm * DD + kk + ka);
            if (A2) {
                float4 a2 = *(const float4*)(A2 + (size_t)gm * DD + kk + ka);
                av.x += a2.x; av.y += a2.y; av.z += a2.z; av.w += a2.w;
            }
        }
        As[ka + 0][ra] = av.x;
        As[ka + 1][ra] = av.y;
        As[ka + 2][ra] = av.z;
        As[ka + 3][ra] = av.w;
#pragma unroll
        for (int i = 0; i < 2; i++) {
            int idx = tid * 2 + i;
            int n = idx >> 2;
            int kq = (idx & 3) * 4;
            float4 wv = *(const float4*)(W + (size_t)n * ldW + kk + kq);
            Bs[kq + 0][n] = wv.x;
            Bs[kq + 1][n] = wv.y;
            Bs[kq + 2][n] = wv.z;
            Bs[kq + 3][n] = wv.w;
        }
        __syncthreads();
#pragma unroll
        for (int k = 0; k < 16; k++) {
            const u64* ap = (const u64*)&As[k][tm * 8];
            u64 a0 = ap[0], a1 = ap[1], a2 = ap[2], a3 = ap[3];
            float4 bv = *(const float4*)&Bs[k][tn * 4];
            u64 b0 = dup2(bv.x), b1 = dup2(bv.y), b2 = dup2(bv.z), b3 = dup2(bv.w);
            fma2(acc[0][0], a0, b0); fma2(acc[0][1], a0, b1);
            fma2(acc[0][2], a0, b2); fma2(acc[0][3], a0, b3);
            fma2(acc[1][0], a1, b0); fma2(acc[1][1], a1, b1);
            fma2(acc[1][2], a1, b2); fma2(acc[1][3], a1, b3);
            fma2(acc[2][0], a2, b0); fma2(acc[2][1], a2, b1);
            fma2(acc[2][2], a2, b2); fma2(acc[2][3], a2, b3);
            fma2(acc[3][0], a3, b0); fma2(acc[3][1], a3, b1);
            fma2(acc[3][2], a3, b2); fma2(acc[3][3], a3, b3);
        }
        __syncthreads();
    }

    float bvals[4];
#pragma unroll
    for (int j = 0; j < 4; j++) bvals[j] = bias ? bias[tn * 4 + j] : 0.f;

#pragma unroll
    for (int p = 0; p < 4; p++) {
        int mA = m0 + tm * 8 + p * 2;
#pragma unroll
        for (int q = 0; q < 2; q++) {
            int m = mA + q;
            if (m >= M) continue;
            float rs = rowScale ? rowScale[m] : 1.f;
            float4 cp = make_float4(0.f, 0.f, 0.f, 0.f);
            if (Cprev) cp = *(const float4*)(Cprev + (size_t)m * DD + tn * 4);
            float4 ca = make_float4(0.f, 0.f, 0.f, 0.f);
            if (Cadd) ca = *(const float4*)(Cadd + (size_t)m * DD + tn * 4);
            float r0 = q ? hi32(acc[p][0]) : lo32(acc[p][0]);
            float r1 = q ? hi32(acc[p][1]) : lo32(acc[p][1]);
            float r2 = q ? hi32(acc[p][2]) : lo32(acc[p][2]);
            float r3 = q ? hi32(acc[p][3]) : lo32(acc[p][3]);
            float v0 = (r0 + bvals[0] + cp.x) * rs + ca.x;
            float v1 = (r1 + bvals[1] + cp.y) * rs + ca.y;
            float v2 = (r2 + bvals[2] + cp.z) * rs + ca.z;
            float v3 = (r3 + bvals[3] + cp.w) * rs + ca.w;
            if (doRelu) {
                v0 = fmaxf(v0, 0.f); v1 = fmaxf(v1, 0.f);
                v2 = fmaxf(v2, 0.f); v3 = fmaxf(v3, 0.f);
            }
            *(float4*)(C + (size_t)m * DD + tn * 4) = make_float4(v0, v1, v2, v3);
        }
    }
}

// ---------------- host side ----------------
static inline int grid_items(int n) {
    int warps = (n + 3) / 4;
    return (warps + 7) / 8;
}

// Streams/events created once on first call; identical launch DAG every call.
static cudaStream_t g_s1 = nullptr;
static cudaEvent_t g_eFork = nullptr, g_eDC = nullptr, g_eB = nullptr;

extern "C" void kernel_launch(void* const* d_in, const int* in_sizes, int n_in,
                              void* d_out, int out_size) {
    const float* vfeat   = (const float*)d_in[0];
    const float* efeat   = (const float*)d_in[1];
    const float* invDV   = (const float*)d_in[2];
    const float* invDE   = (const float*)d_in[3];
    const int*   inc_src = (const int*)d_in[4];
    const int*   inc_dst = (const int*)d_in[5];
    const int*   emat_rows = (const int*)d_in[6];
    const int*   emat_cols = (const int*)d_in[7];
    const float* emat_vals = (const float*)d_in[8];
    const int*   vmat_rows = (const int*)d_in[9];
    const int*   vmat_cols = (const int*)d_in[10];
    const float* vmat_vals = (const float*)d_in[11];
    const float* Wv      = (const float*)d_in[12];
    const float* We      = (const float*)d_in[13];
    const float* psi1_W  = (const float*)d_in[14];
    const float* psi1_b  = (const float*)d_in[15];
    const float* psi2_W  = (const float*)d_in[16];
    const float* psi2_b  = (const float*)d_in[17];

    if (!g_s1) {
        cudaStreamCreateWithFlags(&g_s1, cudaStreamNonBlocking);
        cudaEventCreateWithFlags(&g_eFork, cudaEventDisableTiming);
        cudaEventCreateWithFlags(&g_eDC,   cudaEventDisableTiming);
        cudaEventCreateWithFlags(&g_eB,    cudaEventDisableTiming);
    }

    float* base = nullptr;
    cudaGetSymbolAddress((void**)&base, g_scratch);
    float* U     = base + OFF_U;
    float* T     = base + OFF_T;
    float* emA   = base + OFF_EMA;
    float* dw    = base + OFF_DW;
    float* cnt   = base + OFF_CNT;
    float* v2    = base + OFF_V2;
    float* v3    = base + OFF_V3;
    float* e2acc = base + OFF_E2ACC;
    float* A     = base + OFF_A;
    float* ew    = base + OFF_EW;
    float* B1    = base + OFF_B1;
    float* e2    = base + OFF_E2;

    float* vout = (float*)d_out;               // [NN,128]
    float* eout = vout + ND;                   // [NE,128]

    // ---- memsets that gate BOTH chains (dw/cnt live in zero-region A) ----
    cudaMemsetAsync(base, 0, ZEROA_LEN * sizeof(float));        // U,T,emA,dw,cnt
    cudaMemsetAsync(vout, 0, ND * sizeof(float));

    // ---- fork: stream 1 joins the capture after zero-region A is done ----
    cudaEventRecord(g_eFork, 0);
    cudaStreamWaitEvent(g_s1, g_eFork, 0);

    // ===== stream 1 (chain B): deg/cnt, v2 -> v3 -> e2acc, B1 GEMM =====
    cudaMemsetAsync(base + OFF_V2, 0, ZEROB_LEN * sizeof(float), g_s1);  // v2,v3,e2acc
    deg_cnt_kernel<<<(NNZI + 255) / 256, 256, 0, g_s1>>>(inc_src, inc_dst, invDV, dw, cnt, NNZI);
    cudaEventRecord(g_eDC, g_s1);                  // dw,cnt ready
    scatter_kernel<<<grid_items(NNZI), 256, 0, g_s1>>>(inc_dst, inc_src, nullptr, nullptr, efeat, v2, NNZI);
    scatter_kernel<<<grid_items(NNZV), 256, 0, g_s1>>>(vmat_cols, vmat_rows, vmat_vals, nullptr, v2, v3, NNZV);
    scatter_kernel<<<grid_items(NNZI), 256, 0, g_s1>>>(inc_src, inc_dst, nullptr, nullptr, v3, e2acc, NNZI);
    gemm_kernel<<<(NE + 63) / 64, 256, 0, g_s1>>>(efeat, nullptr, psi2_W + 128, 256, psi2_b, cnt, nullptr, nullptr, B1, NE, 0);
    cudaEventRecord(g_eB, g_s1);

    // ===== stream 0 (chain A) =====
    // U[dst] += invDV[src] * vfeat[src]
    scatter_kernel<<<grid_items(NNZI), 256>>>(inc_src, inc_dst, nullptr, invDV, vfeat, U, NNZI);
    // A = dw .* (efeat @ W1e.T + b1)   (needs dw from s1)
    cudaStreamWaitEvent(0, g_eDC, 0);
    gemm_kernel<<<(NE + 63) / 64, 256>>>(efeat, nullptr, psi1_W + 128, 256, psi1_b, dw, nullptr, nullptr, A, NE, 0);
    // A += U @ W1v.T
    gemm_kernel<<<(NE + 63) / 64, 256>>>(U, nullptr, psi1_W, 256, nullptr, nullptr, A, nullptr, A, NE, 0);
    // emA = emat @ A
    scatter_kernel<<<grid_items(NNZE), 256>>>(emat_cols, emat_rows, emat_vals, nullptr, A, emA, NNZE);
    // ew = (emA + efeat) @ Wv.T
    gemm_kernel<<<(NE + 63) / 64, 256>>>(emA, efeat, Wv, 128, nullptr, nullptr, nullptr, nullptr, ew, NE, 0);
    // vout[src] += ew[dst]
    scatter_kernel<<<grid_items(NNZI), 256>>>(inc_dst, inc_src, nullptr, nullptr, ew, vout, NNZI);
    // vout = relu(vout)  -> final vfeat_out
    relu_kernel<<<(int)((ND / 4 + 255) / 256), 256>>>((float4*)vout, (int)(ND / 4));
    // T[dst] += vout[src]
    scatter_kernel<<<grid_items(NNZI), 256>>>(inc_src, inc_dst, nullptr, nullptr, vout, T, NNZI);
    // join chain B, then: e2 = invDE .* (T @ W2v.T + B1) + e2acc
    cudaStreamWaitEvent(0, g_eB, 0);
    gemm_kernel<<<(NE + 63) / 64, 256>>>(T, nullptr, psi2_W, 256, nullptr, invDE, B1, e2acc, e2, NE, 0);
    // eout = relu(e2 @ We.T)
    gemm_kernel<<<(NE + 63) / 64, 256>>>(e2, nullptr, We, 128, nullptr, nullptr, nullptr, nullptr, eout, NE, 1);
}